// round 6
// baseline (speedup 1.0000x reference)
#include <cuda_runtime.h>

// Noisy LIF spiking neuron scan — R5: exact R1 body (best DRAM%=84.1), tpb=512.
//   u = 0.5*u + x[t] - 0.5*noise[t] ; o = (u > 1) ; u = o ? 0 : u
//
// Lessons R1-R4: every manual ILP restructuring (CH-batching, prefetch
// pipeline) raised regs, cut occupancy, and LOST DRAM bandwidth vs the plain
// rolled loop (regs=28). Block-size was the only axis that moved ncu dur at
// equal occupancy (256 > 128). This round: plain body, tpb=512 (exact grid,
// no bounds check), fused noise subtract via fmaf(-0.5, n, .) which is
// bit-equivalent (0.5*n is exact).

static constexpr int B  = 16;
static constexpr int T  = 64;
static constexpr int N  = 65536;
static constexpr int N4 = N / 4;     // float4 lanes per (b, t) row

__global__ __launch_bounds__(512) void lif_kernel(
    const float4* __restrict__ x,
    const float4* __restrict__ noise,
    float4* __restrict__ out)
{
    int idx = blockIdx.x * blockDim.x + threadIdx.x;   // 0 .. B*N4-1 (exact)

    int b  = idx >> 14;          // / N4 (16384)
    int n4 = idx & (N4 - 1);     // % N4

    const size_t base = (size_t)b * T * N4 + n4;
    const float4* __restrict__ xp = x     + base;
    const float4* __restrict__ np = noise + base;
    float4*       __restrict__ op = out   + base;

    float ux = 0.f, uy = 0.f, uz = 0.f, uw = 0.f;

#pragma unroll
    for (int t = 0; t < T; t++) {
        const float4 xv = __ldcs(xp + t * N4);
        const float4 nv = __ldcs(np + t * N4);

        float4 o;

        ux  = fmaf(-0.5f, nv.x, fmaf(0.5f, ux, xv.x));
        o.x = (ux > 1.0f) ? 1.0f : 0.0f;
        ux  = (ux > 1.0f) ? 0.0f : ux;

        uy  = fmaf(-0.5f, nv.y, fmaf(0.5f, uy, xv.y));
        o.y = (uy > 1.0f) ? 1.0f : 0.0f;
        uy  = (uy > 1.0f) ? 0.0f : uy;

        uz  = fmaf(-0.5f, nv.z, fmaf(0.5f, uz, xv.z));
        o.z = (uz > 1.0f) ? 1.0f : 0.0f;
        uz  = (uz > 1.0f) ? 0.0f : uz;

        uw  = fmaf(-0.5f, nv.w, fmaf(0.5f, uw, xv.w));
        o.w = (uw > 1.0f) ? 1.0f : 0.0f;
        uw  = (uw > 1.0f) ? 0.0f : uw;

        __stcs(op + t * N4, o);
    }
}

extern "C" void kernel_launch(void* const* d_in, const int* in_sizes, int n_in,
                              void* d_out, int out_size)
{
    const float4* x     = (const float4*)d_in[0];
    const float4* noise = (const float4*)d_in[1];
    float4*       out   = (float4*)d_out;

    const int total_threads = B * N4;    // 262144
    const int tpb = 512;
    const int blocks = total_threads / tpb;  // 512, exact

    lif_kernel<<<blocks, tpb>>>(x, noise, out);
}

// round 7
// speedup vs baseline: 1.0227x; 1.0227x over previous
#include <cuda_runtime.h>

// Noisy LIF spiking neuron scan — R6: proven R1 body + write-through stores.
//   u = 0.5*u + x[t] - 0.5*noise[t] ; o = (u > 1) ; u = o ? 0 : u
//
// R1-R5 mapped the surface: plain rolled loop (regs=28, occ ~82%) is optimal;
// all ILP restructuring lost; block size 128<256==512; ncu pinned at
// DRAM=84.1% / 115 us. Last lever: stores. 256 MB of output is written once,
// never read — __stwt (write-through) avoids L2 write-allocate churn so the
// DRAM scheduler sees cleaner read/write phases. Loads stay __ldcs
// (evict-first streaming). Exact grid, no bounds check.

static constexpr int B  = 16;
static constexpr int T  = 64;
static constexpr int N  = 65536;
static constexpr int N4 = N / 4;     // float4 lanes per (b, t) row

__global__ __launch_bounds__(256) void lif_kernel(
    const float4* __restrict__ x,
    const float4* __restrict__ noise,
    float4* __restrict__ out)
{
    int idx = blockIdx.x * blockDim.x + threadIdx.x;   // 0 .. B*N4-1 (exact)

    int b  = idx >> 14;          // / N4 (16384)
    int n4 = idx & (N4 - 1);     // % N4

    const size_t base = (size_t)b * T * N4 + n4;
    const float4* __restrict__ xp = x     + base;
    const float4* __restrict__ np = noise + base;
    float4*       __restrict__ op = out   + base;

    float ux = 0.f, uy = 0.f, uz = 0.f, uw = 0.f;

#pragma unroll
    for (int t = 0; t < T; t++) {
        const float4 xv = __ldcs(xp + t * N4);
        const float4 nv = __ldcs(np + t * N4);

        float4 o;

        ux  = fmaf(-0.5f, nv.x, fmaf(0.5f, ux, xv.x));
        o.x = (ux > 1.0f) ? 1.0f : 0.0f;
        ux  = (ux > 1.0f) ? 0.0f : ux;

        uy  = fmaf(-0.5f, nv.y, fmaf(0.5f, uy, xv.y));
        o.y = (uy > 1.0f) ? 1.0f : 0.0f;
        uy  = (uy > 1.0f) ? 0.0f : uy;

        uz  = fmaf(-0.5f, nv.z, fmaf(0.5f, uz, xv.z));
        o.z = (uz > 1.0f) ? 1.0f : 0.0f;
        uz  = (uz > 1.0f) ? 0.0f : uz;

        uw  = fmaf(-0.5f, nv.w, fmaf(0.5f, uw, xv.w));
        o.w = (uw > 1.0f) ? 1.0f : 0.0f;
        uw  = (uw > 1.0f) ? 0.0f : uw;

        __stwt(op + t * N4, o);
    }
}

extern "C" void kernel_launch(void* const* d_in, const int* in_sizes, int n_in,
                              void* d_out, int out_size)
{
    const float4* x     = (const float4*)d_in[0];
    const float4* noise = (const float4*)d_in[1];
    float4*       out   = (float4*)d_out;

    const int total_threads = B * N4;        // 262144
    const int tpb = 256;
    const int blocks = total_threads / tpb;  // 1024, exact

    lif_kernel<<<blocks, tpb>>>(x, noise, out);
}